// round 1
// baseline (speedup 1.0000x reference)
#include <cuda_runtime.h>
#include <cstdint>

// Problem constants
#define D   1024
#define H   16
#define DH  64
#define FF  4096
#define SEQ 2048
#define MAXTOK 8192   // B=4 * S=2048

// ---------------- scratch (static device globals; no allocation) ----------------
__device__ float g_xln [MAXTOK * D];        // LN1 output
__device__ float g_qkv [MAXTOK * 3 * D];    // QKV
__device__ float g_attn[MAXTOK * D];        // attention output (pre-proj)
__device__ float g_res [MAXTOK * D];        // residual after attention
__device__ float g_mln [MAXTOK * D];        // LN2 output
__device__ float g_fc  [(size_t)MAXTOK * FF]; // gelu(fc)

// ---------------- LayerNorm: one block per row ----------------
__global__ __launch_bounds__(256) void ln_kernel(const float* __restrict__ in,
                                                 const float* __restrict__ gw,
                                                 const float* __restrict__ bw,
                                                 float* __restrict__ out)
{
    __shared__ float red0[8], red1[8];
    int row = blockIdx.x, tid = threadIdx.x;
    const float4* x4 = (const float4*)(in + (size_t)row * D);
    float4 v = x4[tid];                      // 256 threads * 4 = 1024
    float s  = v.x + v.y + v.z + v.w;
    float ss = v.x*v.x + v.y*v.y + v.z*v.z + v.w*v.w;
    #pragma unroll
    for (int o = 16; o; o >>= 1) {
        s  += __shfl_xor_sync(0xffffffffu, s,  o);
        ss += __shfl_xor_sync(0xffffffffu, ss, o);
    }
    if ((tid & 31) == 0) { red0[tid >> 5] = s; red1[tid >> 5] = ss; }
    __syncthreads();
    s = 0.f; ss = 0.f;
    #pragma unroll
    for (int i = 0; i < 8; i++) { s += red0[i]; ss += red1[i]; }
    float mean = s * (1.f / D);
    float var  = ss * (1.f / D) - mean * mean;
    float rstd = rsqrtf(var + 1e-5f);
    float4 gv = ((const float4*)gw)[tid];
    float4 bv = ((const float4*)bw)[tid];
    float4 o4;
    o4.x = (v.x - mean) * rstd * gv.x + bv.x;
    o4.y = (v.y - mean) * rstd * gv.y + bv.y;
    o4.z = (v.z - mean) * rstd * gv.z + bv.z;
    o4.w = (v.w - mean) * rstd * gv.w + bv.w;
    ((float4*)(out + (size_t)row * D))[tid] = o4;
}

// ---------------- Tiled SGEMM: C[M,N] = A[M,K] @ B[K,N] + epilogue ----------------
// EPI 0: + bias ; EPI 1: gelu_new(+bias) ; EPI 2: + bias + res
template<int EPI>
__global__ __launch_bounds__(256) void gemm_kernel(const float* __restrict__ A,
                                                   const float* __restrict__ B,
                                                   const float* __restrict__ bias,
                                                   const float* __restrict__ res,
                                                   float* __restrict__ C,
                                                   int M, int N, int K)
{
    __shared__ float As[8 * 128];   // transposed: As[k][m]
    __shared__ float Bs[8 * 128];   // Bs[k][n]
    int tid = threadIdx.x;
    int bm = blockIdx.y << 7, bn = blockIdx.x << 7;
    int rt = tid >> 4, ct = tid & 15;          // 16x16 thread grid, 8x8 microtile

    float acc[8][8];
    #pragma unroll
    for (int i = 0; i < 8; i++)
        #pragma unroll
        for (int j = 0; j < 8; j++) acc[i][j] = 0.f;

    int arow = tid >> 1, acol = (tid & 1) << 2;     // A tile: 128 rows x 8 cols
    int brow = tid >> 5, bcol = (tid & 31) << 2;    // B tile: 8 rows x 128 cols
    const float* Aptr = A + (size_t)(bm + arow) * K + acol;
    const float* Bptr = B + (size_t)brow * N + bn + bcol;

    for (int k0 = 0; k0 < K; k0 += 8) {
        float4 av = *(const float4*)Aptr; Aptr += 8;
        float4 bv = *(const float4*)(Bptr + (size_t)k0 * N);
        As[(acol + 0) * 128 + arow] = av.x;
        As[(acol + 1) * 128 + arow] = av.y;
        As[(acol + 2) * 128 + arow] = av.z;
        As[(acol + 3) * 128 + arow] = av.w;
        *(float4*)(Bs + brow * 128 + bcol) = bv;
        __syncthreads();
        #pragma unroll
        for (int k = 0; k < 8; k++) {
            float a[8], b[8];
            *(float4*)(a)     = *(const float4*)&As[k * 128 + rt * 8];
            *(float4*)(a + 4) = *(const float4*)&As[k * 128 + rt * 8 + 4];
            *(float4*)(b)     = *(const float4*)&Bs[k * 128 + ct * 8];
            *(float4*)(b + 4) = *(const float4*)&Bs[k * 128 + ct * 8 + 4];
            #pragma unroll
            for (int i = 0; i < 8; i++)
                #pragma unroll
                for (int j = 0; j < 8; j++)
                    acc[i][j] += a[i] * b[j];
        }
        __syncthreads();
    }

    const float GC = 0.7978845608028654f;
    #pragma unroll
    for (int i = 0; i < 8; i++) {
        int row = bm + rt * 8 + i;
        #pragma unroll
        for (int j = 0; j < 8; j++) {
            int col = bn + ct * 8 + j;
            float v = acc[i][j] + bias[col];
            if (EPI == 1) {
                float x3 = v * v * v;
                v = 0.5f * v * (1.f + tanhf(GC * (v + 0.044715f * x3)));
            }
            if (EPI == 2) v += res[(size_t)row * N + col];
            C[(size_t)row * N + col] = v;
        }
    }
}

// ---------------- Flash attention (causal), fp32, 64x64 tiles ----------------
// grid: (S/64, H, B), block 256.  qkv: [tok, 3*D], out: [tok, D]
__global__ __launch_bounds__(256) void attn_kernel(const float* __restrict__ qkv,
                                                   float* __restrict__ out)
{
    extern __shared__ float sm[];
    float* Qs = sm;               // 64 x 65
    float* Ks = sm + 64 * 65;
    float* Vs = sm + 2 * 64 * 65;
    float* Ps = sm + 3 * 64 * 65;

    int b = blockIdx.z, h = blockIdx.y;
    int q0 = blockIdx.x << 6;
    int tid = threadIdx.x, ty = tid >> 4, tx = tid & 15;
    const size_t base = (size_t)b * SEQ * (3 * D);

    // load Q tile (scaled by 1/sqrt(DH))
    for (int i = tid; i < 1024; i += 256) {           // 1024 float4 slots
        int r = i >> 4, c4 = (i & 15) << 2;
        float4 v = *(const float4*)(qkv + base + (size_t)(q0 + r) * (3 * D) + h * DH + c4);
        Qs[r * 65 + c4 + 0] = v.x * 0.125f;
        Qs[r * 65 + c4 + 1] = v.y * 0.125f;
        Qs[r * 65 + c4 + 2] = v.z * 0.125f;
        Qs[r * 65 + c4 + 3] = v.w * 0.125f;
    }

    float m_i[4], l_i[4], o[4][4];
    #pragma unroll
    for (int i = 0; i < 4; i++) {
        m_i[i] = -1e30f; l_i[i] = 0.f;
        #pragma unroll
        for (int j = 0; j < 4; j++) o[i][j] = 0.f;
    }

    int ntiles = (q0 >> 6) + 1;
    for (int kt = 0; kt < ntiles; kt++) {
        int k0 = kt << 6;
        __syncthreads();
        for (int i = tid; i < 1024; i += 256) {
            int r = i >> 4, c4 = (i & 15) << 2;
            size_t rowoff = base + (size_t)(k0 + r) * (3 * D) + h * DH + c4;
            float4 kv = *(const float4*)(qkv + rowoff + D);
            float4 vv = *(const float4*)(qkv + rowoff + 2 * D);
            Ks[r * 65 + c4 + 0] = kv.x; Ks[r * 65 + c4 + 1] = kv.y;
            Ks[r * 65 + c4 + 2] = kv.z; Ks[r * 65 + c4 + 3] = kv.w;
            Vs[r * 65 + c4 + 0] = vv.x; Vs[r * 65 + c4 + 1] = vv.y;
            Vs[r * 65 + c4 + 2] = vv.z; Vs[r * 65 + c4 + 3] = vv.w;
        }
        __syncthreads();

        // S = Q K^T  (4x4 per thread)
        float s[4][4];
        #pragma unroll
        for (int i = 0; i < 4; i++)
            #pragma unroll
            for (int j = 0; j < 4; j++) s[i][j] = 0.f;
        #pragma unroll 4
        for (int d = 0; d < 64; d++) {
            float q[4], k[4];
            #pragma unroll
            for (int i = 0; i < 4; i++) q[i] = Qs[(ty * 4 + i) * 65 + d];
            #pragma unroll
            for (int j = 0; j < 4; j++) k[j] = Ks[(tx * 4 + j) * 65 + d];
            #pragma unroll
            for (int i = 0; i < 4; i++)
                #pragma unroll
                for (int j = 0; j < 4; j++)
                    s[i][j] += q[i] * k[j];
        }
        if (kt == ntiles - 1) {   // diagonal tile: causal mask
            #pragma unroll
            for (int i = 0; i < 4; i++)
                #pragma unroll
                for (int j = 0; j < 4; j++)
                    if (k0 + tx * 4 + j > q0 + ty * 4 + i) s[i][j] = -10000.0f;
        }

        // online softmax update
        #pragma unroll
        for (int i = 0; i < 4; i++) {
            float rm = fmaxf(fmaxf(s[i][0], s[i][1]), fmaxf(s[i][2], s[i][3]));
            #pragma unroll
            for (int off = 8; off; off >>= 1)
                rm = fmaxf(rm, __shfl_xor_sync(0xffffffffu, rm, off, 16));
            float mnew = fmaxf(m_i[i], rm);
            float corr = __expf(m_i[i] - mnew);
            float rs = 0.f;
            #pragma unroll
            for (int j = 0; j < 4; j++) {
                float p = __expf(s[i][j] - mnew);
                s[i][j] = p; rs += p;
            }
            #pragma unroll
            for (int off = 8; off; off >>= 1)
                rs += __shfl_xor_sync(0xffffffffu, rs, off, 16);
            l_i[i] = l_i[i] * corr + rs;
            m_i[i] = mnew;
            #pragma unroll
            for (int j = 0; j < 4; j++) o[i][j] *= corr;
        }

        // stage P, then O += P V
        #pragma unroll
        for (int i = 0; i < 4; i++)
            #pragma unroll
            for (int j = 0; j < 4; j++)
                Ps[(ty * 4 + i) * 65 + tx * 4 + j] = s[i][j];
        __syncthreads();
        #pragma unroll 4
        for (int d = 0; d < 64; d++) {
            float p[4], v[4];
            #pragma unroll
            for (int i = 0; i < 4; i++) p[i] = Ps[(ty * 4 + i) * 65 + d];
            #pragma unroll
            for (int j = 0; j < 4; j++) v[j] = Vs[d * 65 + tx * 4 + j];
            #pragma unroll
            for (int i = 0; i < 4; i++)
                #pragma unroll
                for (int j = 0; j < 4; j++)
                    o[i][j] += p[i] * v[j];
        }
    }

    #pragma unroll
    for (int i = 0; i < 4; i++) {
        float inv = 1.f / l_i[i];
        #pragma unroll
        for (int j = 0; j < 4; j++)
            out[(size_t)(b * SEQ + q0 + ty * 4 + i) * D + h * DH + tx * 4 + j] =
                o[i][j] * inv;
    }
}

// ---------------- launch ----------------
extern "C" void kernel_launch(void* const* d_in, const int* in_sizes, int n_in,
                              void* d_out, int out_size)
{
    const float* hs    = (const float*)d_in[0];
    const float* ln1g  = (const float*)d_in[1];
    const float* ln1b  = (const float*)d_in[2];
    const float* wattn = (const float*)d_in[3];
    const float* battn = (const float*)d_in[4];
    const float* wproj = (const float*)d_in[5];
    const float* bproj = (const float*)d_in[6];
    const float* ln2g  = (const float*)d_in[7];
    const float* ln2b  = (const float*)d_in[8];
    const float* wfc   = (const float*)d_in[9];
    const float* bfc   = (const float*)d_in[10];
    const float* wmlp  = (const float*)d_in[11];
    const float* bmlp  = (const float*)d_in[12];
    float* out = (float*)d_out;

    int tokens = in_sizes[0] / D;       // B*S = 8192
    int B = tokens / SEQ;

    float *xln, *qkvb, *attnb, *resb, *mlnb, *fcb;
    cudaGetSymbolAddress((void**)&xln,  g_xln);
    cudaGetSymbolAddress((void**)&qkvb, g_qkv);
    cudaGetSymbolAddress((void**)&attnb,g_attn);
    cudaGetSymbolAddress((void**)&resb, g_res);
    cudaGetSymbolAddress((void**)&mlnb, g_mln);
    cudaGetSymbolAddress((void**)&fcb,  g_fc);

    // LN1
    ln_kernel<<<tokens, 256>>>(hs, ln1g, ln1b, xln);

    // QKV = xln @ w_attn + b_attn   [tokens, 3D]
    gemm_kernel<0><<<dim3((3 * D) / 128, tokens / 128), 256>>>(
        xln, wattn, battn, nullptr, qkvb, tokens, 3 * D, D);

    // attention
    int smem = 4 * 64 * 65 * (int)sizeof(float);
    cudaFuncSetAttribute(attn_kernel, cudaFuncAttributeMaxDynamicSharedMemorySize, smem);
    attn_kernel<<<dim3(SEQ / 64, H, B), 256, smem>>>(qkvb, attnb);

    // resid = hs + attnb @ w_attn_proj + b_attn_proj
    gemm_kernel<2><<<dim3(D / 128, tokens / 128), 256>>>(
        attnb, wproj, bproj, hs, resb, tokens, D, D);

    // LN2
    ln_kernel<<<tokens, 256>>>(resb, ln2g, ln2b, mlnb);

    // fc = gelu_new(mlnb @ w_fc + b_fc)   [tokens, FF]
    gemm_kernel<1><<<dim3(FF / 128, tokens / 128), 256>>>(
        mlnb, wfc, bfc, nullptr, fcb, tokens, FF, D);

    // out = resb + fcb @ w_mlp_proj + b_mlp_proj
    gemm_kernel<2><<<dim3(D / 128, tokens / 128), 256>>>(
        fcb, wmlp, bmlp, resb, out, tokens, D, FF);
}

// round 4
// speedup vs baseline: 1.6046x; 1.6046x over previous
#include <cuda_runtime.h>
#include <cstdint>

// Problem constants
#define D   1024
#define H   16
#define DH  64
#define FF  4096
#define SEQ 2048
#define MAXTOK 8192   // B=4 * S=2048

// ---------------- scratch (static device globals; no allocation) ----------------
__device__ float g_xln [MAXTOK * D];
__device__ float g_qkv [MAXTOK * 3 * D];
__device__ float g_attn[MAXTOK * D];
__device__ float g_res [MAXTOK * D];
__device__ float g_mln [MAXTOK * D];
__device__ float g_fc  [(size_t)MAXTOK * FF];
// transposed weights (Bt[N][K], K-major == col-major B for mma .row.col)
__device__ float g_wattn_t[3 * D * D];
__device__ float g_wproj_t[D * D];
__device__ float g_wfc_t  [FF * D];
__device__ float g_wmlp_t [D * FF];

// ---------------- helpers ----------------
__device__ __forceinline__ uint32_t smem_u32(const void* p){
    uint32_t a;
    asm("{ .reg .u64 t; cvta.to.shared.u64 t, %1; cvt.u32.u64 %0, t; }" : "=r"(a) : "l"(p));
    return a;
}
// round fp32 -> tf32 (round-to-nearest) kept in an f32 container
__device__ __forceinline__ float tf32r(float x){
    uint32_t u; asm("cvt.rna.tf32.f32 %0, %1;" : "=r"(u) : "f"(x));
    return __uint_as_float(u);
}
__device__ __forceinline__ void mma_tf32(float* c, const uint32_t* a, const uint32_t* b){
    asm volatile(
        "mma.sync.aligned.m16n8k8.row.col.f32.tf32.tf32.f32 "
        "{%0,%1,%2,%3}, {%4,%5,%6,%7}, {%8,%9}, {%0,%1,%2,%3};\n"
        : "+f"(c[0]), "+f"(c[1]), "+f"(c[2]), "+f"(c[3])
        : "r"(a[0]), "r"(a[1]), "r"(a[2]), "r"(a[3]), "r"(b[0]), "r"(b[1]));
}
__device__ __forceinline__ void cp16(uint32_t smem_addr, const void* gptr){
    asm volatile("cp.async.cg.shared.global [%0], [%1], 16;" :: "r"(smem_addr), "l"(gptr));
}

// ---------------- transpose: in[R][C] -> out[C][R], rounded to tf32 ----------------
__global__ __launch_bounds__(256) void transpose_kernel(const float* __restrict__ in,
                                                        float* __restrict__ out, int R, int C)
{
    __shared__ float t[32][33];
    int bx = blockIdx.x * 32, by = blockIdx.y * 32;
    int x = threadIdx.x & 31, y0 = threadIdx.x >> 5;
    #pragma unroll
    for (int yy = y0; yy < 32; yy += 8)
        t[yy][x] = in[(size_t)(by + yy) * C + bx + x];
    __syncthreads();
    #pragma unroll
    for (int yy = y0; yy < 32; yy += 8)
        out[(size_t)(bx + yy) * R + by + x] = tf32r(t[x][yy]);
}

// ---------------- LayerNorm (output rounded to tf32: feeds GEMM A) ----------------
__global__ __launch_bounds__(256) void ln_kernel(const float* __restrict__ in,
                                                 const float* __restrict__ gw,
                                                 const float* __restrict__ bw,
                                                 float* __restrict__ out)
{
    __shared__ float red0[8], red1[8];
    int row = blockIdx.x, tid = threadIdx.x;
    const float4* x4 = (const float4*)(in + (size_t)row * D);
    float4 v = x4[tid];
    float s  = v.x + v.y + v.z + v.w;
    float ss = v.x*v.x + v.y*v.y + v.z*v.z + v.w*v.w;
    #pragma unroll
    for (int o = 16; o; o >>= 1) {
        s  += __shfl_xor_sync(0xffffffffu, s,  o);
        ss += __shfl_xor_sync(0xffffffffu, ss, o);
    }
    if ((tid & 31) == 0) { red0[tid >> 5] = s; red1[tid >> 5] = ss; }
    __syncthreads();
    s = 0.f; ss = 0.f;
    #pragma unroll
    for (int i = 0; i < 8; i++) { s += red0[i]; ss += red1[i]; }
    float mean = s * (1.f / D);
    float var  = ss * (1.f / D) - mean * mean;
    float rstd = rsqrtf(var + 1e-5f);
    float4 gv = ((const float4*)gw)[tid];
    float4 bv = ((const float4*)bw)[tid];
    float4 o4;
    o4.x = tf32r((v.x - mean) * rstd * gv.x + bv.x);
    o4.y = tf32r((v.y - mean) * rstd * gv.y + bv.y);
    o4.z = tf32r((v.z - mean) * rstd * gv.z + bv.z);
    o4.w = tf32r((v.w - mean) * rstd * gv.w + bv.w);
    ((float4*)(out + (size_t)row * D))[tid] = o4;
}

// ============== mma.sync tf32 GEMM: C[M,N] = A[M,K] @ Bt[N,K]^T + epilogue ==============
// CTA tile 128x128, 4 warps (2x2), warptile 64x64, BK=32, cp.async double buffer.
// EPI 0: +bias ; 1: gelu(+bias) rounded tf32 ; 2: +bias +res
#define BM 128
#define BN 128
#define BK 32
#define LDT 36                       // padded smem row stride (floats)
#define TBUF (128 * LDT)             // floats per tile buffer
#define GSMEM (4 * TBUF * 4)         // 2 bufs * (A+B) * 4B = 73728

template<int EPI>
__global__ __launch_bounds__(128) void tc_gemm(const float* __restrict__ A,
                                               const float* __restrict__ Bt,
                                               const float* __restrict__ bias,
                                               const float* __restrict__ res,
                                               float* __restrict__ C,
                                               int M, int N_, int K)
{
    extern __shared__ float smem[];
    float* AsBase = smem;                // [2][TBUF]
    float* BsBase = smem + 2 * TBUF;     // [2][TBUF]
    const int tid = threadIdx.x, lane = tid & 31, wid = tid >> 5;
    const int wm = (wid >> 1) * 64, wn = (wid & 1) * 64;
    const int bm = blockIdx.y * BM, bn = blockIdx.x * BN;
    const int nch = K / BK;

    const float* Ag = A  + (size_t)bm * K;
    const float* Bg = Bt + (size_t)bn * K;

    float acc[4][8][4];
    #pragma unroll
    for (int mf = 0; mf < 4; mf++)
        #pragma unroll
        for (int nf = 0; nf < 8; nf++)
            #pragma unroll
            for (int q = 0; q < 4; q++) acc[mf][nf][q] = 0.f;

    // chunk loader: 128 rows x 32 floats for A and B each (8 float4 per thread each)
    auto load_chunk = [&](int c, int buf) {
        float* dA = AsBase + buf * TBUF;
        float* dB = BsBase + buf * TBUF;
        const float* a0 = Ag + c * BK;
        const float* b0 = Bg + c * BK;
        #pragma unroll
        for (int i = 0; i < 8; i++) {
            int slot = i * 128 + tid;
            int r = slot >> 3, u = slot & 7;
            cp16(smem_u32(dA + r * LDT + u * 4), a0 + (size_t)r * K + u * 4);
            cp16(smem_u32(dB + r * LDT + u * 4), b0 + (size_t)r * K + u * 4);
        }
        asm volatile("cp.async.commit_group;" ::: "memory");
    };

    load_chunk(0, 0);

    for (int c = 0; c < nch; c++) {
        if (c + 1 < nch) {
            load_chunk(c + 1, (c + 1) & 1);
            asm volatile("cp.async.wait_group 1;" ::: "memory");
        } else {
            asm volatile("cp.async.wait_group 0;" ::: "memory");
        }
        __syncthreads();
        const float* cA = AsBase + (c & 1) * TBUF;
        const float* cB = BsBase + (c & 1) * TBUF;
        #pragma unroll
        for (int ks = 0; ks < 4; ks++) {
            const int k0 = ks * 8 + (lane & 3);
            uint32_t a[4][4], b[8][2];
            #pragma unroll
            for (int mf = 0; mf < 4; mf++) {
                const float* p = cA + (wm + mf * 16 + (lane >> 2)) * LDT + k0;
                a[mf][0] = __float_as_uint(p[0]);
                a[mf][1] = __float_as_uint(p[8 * LDT]);
                a[mf][2] = __float_as_uint(p[4]);
                a[mf][3] = __float_as_uint(p[8 * LDT + 4]);
            }
            #pragma unroll
            for (int nf = 0; nf < 8; nf++) {
                const float* p = cB + (wn + nf * 8 + (lane >> 2)) * LDT + k0;
                b[nf][0] = __float_as_uint(p[0]);
                b[nf][1] = __float_as_uint(p[4]);
            }
            #pragma unroll
            for (int mf = 0; mf < 4; mf++)
                #pragma unroll
                for (int nf = 0; nf < 8; nf++)
                    mma_tf32(acc[mf][nf], a[mf], b[nf]);
        }
        __syncthreads();
    }

    // epilogue
    const float GC = 0.7978845608028654f;
    #pragma unroll
    for (int mf = 0; mf < 4; mf++) {
        #pragma unroll
        for (int half = 0; half < 2; half++) {
            int row = bm + wm + mf * 16 + (lane >> 2) + half * 8;
            float* Crow = C + (size_t)row * N_ + bn + wn;
            const float* Rrow = res + (size_t)row * N_ + bn + wn;
            #pragma unroll
            for (int nf = 0; nf < 8; nf++) {
                int col = nf * 8 + 2 * (lane & 3);
                float2 v;
                v.x = acc[mf][nf][half * 2 + 0] + bias[bn + wn + col];
                v.y = acc[mf][nf][half * 2 + 1] + bias[bn + wn + col + 1];
                if (EPI == 1) {
                    v.x = tf32r(0.5f * v.x * (1.f + tanhf(GC * (v.x + 0.044715f * v.x * v.x * v.x))));
                    v.y = tf32r(0.5f * v.y * (1.f + tanhf(GC * (v.y + 0.044715f * v.y * v.y * v.y))));
                }
                if (EPI == 2) {
                    float2 rv = *(const float2*)(Rrow + col);
                    v.x += rv.x; v.y += rv.y;
                }
                *(float2*)(Crow + col) = v;
            }
        }
    }
}

// ============== Flash attention (causal), fp32, Q-tile 128 x K-tile 64 ==============
// 128 threads, 8x8 microtile. XOR-swizzled float4 smem layout (conflict-free).
__device__ __forceinline__ int aswz(int r, int u){ return (r << 4) + (u ^ ((r >> 3) & 7)); }

__global__ __launch_bounds__(128) void attn_kernel(const float* __restrict__ qkv,
                                                   float* __restrict__ out)
{
    extern __shared__ float4 sm4[];
    float4* Qs = sm4;            // 128 rows x 16 units
    float4* Ks = sm4 + 2048;     // 64 x 16
    float4* Vs = sm4 + 3072;     // 64 x 16
    float4* Ps = sm4 + 4096;     // 128 x 16
    const int b = blockIdx.z, h = blockIdx.y, q0 = blockIdx.x << 7;
    const int tid = threadIdx.x;
    const int ty = tid >> 3, tx = tid & 7;
    const size_t base = (size_t)b * SEQ * (3 * D) + h * DH;

    for (int s = tid; s < 2048; s += 128) {
        int r = s >> 4, u = s & 15;
        float4 v = *(const float4*)(qkv + base + (size_t)(q0 + r) * (3 * D) + u * 4);
        v.x *= 0.125f; v.y *= 0.125f; v.z *= 0.125f; v.w *= 0.125f;
        Qs[aswz(r, u)] = v;
    }

    float m_i[8], l_i[8], o[8][8];
    #pragma unroll
    for (int i = 0; i < 8; i++) {
        m_i[i] = -1e30f; l_i[i] = 0.f;
        #pragma unroll
        for (int j = 0; j < 8; j++) o[i][j] = 0.f;
    }

    const int ntiles = (q0 >> 6) + 2;
    for (int kt = 0; kt < ntiles; kt++) {
        const int k0 = kt << 6;
        __syncthreads();
        for (int s = tid; s < 1024; s += 128) {
            int r = s >> 4, u = s & 15;
            const float* p = qkv + base + (size_t)(k0 + r) * (3 * D) + u * 4;
            Ks[aswz(r, u)] = *(const float4*)(p + D);
            Vs[aswz(r, u)] = *(const float4*)(p + 2 * D);
        }
        __syncthreads();

        float sc[8][8];
        #pragma unroll
        for (int i = 0; i < 8; i++)
            #pragma unroll
            for (int j = 0; j < 8; j++) sc[i][j] = 0.f;
        #pragma unroll
        for (int d4 = 0; d4 < 16; d4++) {
            float4 kv[8];
            #pragma unroll
            for (int j = 0; j < 8; j++) kv[j] = Ks[aswz(tx * 8 + j, d4)];
            #pragma unroll
            for (int i = 0; i < 8; i++) {
                float4 qv = Qs[aswz(ty * 8 + i, d4)];
                #pragma unroll
                for (int j = 0; j < 8; j++) {
                    float t = sc[i][j];
                    t = fmaf(qv.x, kv[j].x, t);
                    t = fmaf(qv.y, kv[j].y, t);
                    t = fmaf(qv.z, kv[j].z, t);
                    t = fmaf(qv.w, kv[j].w, t);
                    sc[i][j] = t;
                }
            }
        }

        if (kt >= ntiles - 2) {
            #pragma unroll
            for (int i = 0; i < 8; i++)
                #pragma unroll
                for (int j = 0; j < 8; j++)
                    if (k0 + tx * 8 + j > q0 + ty * 8 + i) sc[i][j] = -10000.0f;
        }

        #pragma unroll
        for (int i = 0; i < 8; i++) {
            float rm = sc[i][0];
            #pragma unroll
            for (int j = 1; j < 8; j++) rm = fmaxf(rm, sc[i][j]);
            rm = fmaxf(rm, __shfl_xor_sync(0xffffffffu, rm, 4, 8));
            rm = fmaxf(rm, __shfl_xor_sync(0xffffffffu, rm, 2, 8));
            rm = fmaxf(rm, __shfl_xor_sync(0xffffffffu, rm, 1, 8));
            float mnew = fmaxf(m_i[i], rm);
            float corr = __expf(m_i[i] - mnew);
            float rs = 0.f;
            #pragma unroll
            for (int j = 0; j < 8; j++) {
                float p = __expf(sc[i][j] - mnew);
                sc[i][j] = p; rs += p;
            }
            rs += __shfl_xor_sync(0xffffffffu, rs, 4, 8);
            rs += __shfl_xor_sync(0xffffffffu, rs, 2, 8);
            rs += __shfl_xor_sync(0xffffffffu, rs, 1, 8);
            l_i[i] = l_i[i] * corr + rs;
            m_i[i] = mnew;
            #pragma unroll
            for (int j = 0; j < 8; j++) o[i][j] *= corr;
        }

        #pragma unroll
        for (int i = 0; i < 8; i++) {
            int r = ty * 8 + i;
            Ps[aswz(r, 2 * tx)]     = make_float4(sc[i][0], sc[i][1], sc[i][2], sc[i][3]);
            Ps[aswz(r, 2 * tx + 1)] = make_float4(sc[i][4], sc[i][5], sc[i][6], sc[i][7]);
        }
        __syncthreads();

        #pragma unroll
        for (int k4 = 0; k4 < 16; k4++) {
            float4 v0[4], v1[4];
            #pragma unroll
            for (int m = 0; m < 4; m++) {
                v0[m] = Vs[aswz(k4 * 4 + m, 2 * tx)];
                v1[m] = Vs[aswz(k4 * 4 + m, 2 * tx + 1)];
            }
            #pragma unroll
            for (int i = 0; i < 8; i++) {
                float4 pv = Ps[aswz(ty * 8 + i, k4)];
                float pm[4] = {pv.x, pv.y, pv.z, pv.w};
                #pragma unroll
                for (int m = 0; m < 4; m++) {
                    o[i][0] = fmaf(pm[m], v0[m].x, o[i][0]);
                    o[i][1] = fmaf(pm[m], v0[m].y, o[i][1]);
                    o[i][2] = fmaf(pm[m], v0[m].z, o[i][2]);
                    o[i][3] = fmaf(pm[m], v0[m].w, o[i][3]);
                    o[i][4] = fmaf(pm[m], v1[m].x, o[i][4]);
                    o[i][5] = fmaf(pm[m], v1[m].y, o[i][5]);
                    o[i][6] = fmaf(pm[m], v1[m].z, o[i][6]);
                    o[i][7] = fmaf(pm[m], v1[m].w, o[i][7]);
                }
            }
        }
    }

    #pragma unroll
    for (int i = 0; i < 8; i++) {
        float inv = 1.f / l_i[i];
        float* orow = out + (size_t)(b * SEQ + q0 + ty * 8 + i) * D + h * DH + tx * 8;
        // rounded to tf32: feeds the attn-proj GEMM as A operand
        *(float4*)(orow)     = make_float4(tf32r(o[i][0] * inv), tf32r(o[i][1] * inv),
                                           tf32r(o[i][2] * inv), tf32r(o[i][3] * inv));
        *(float4*)(orow + 4) = make_float4(tf32r(o[i][4] * inv), tf32r(o[i][5] * inv),
                                           tf32r(o[i][6] * inv), tf32r(o[i][7] * inv));
    }
}

// ---------------- launch ----------------
extern "C" void kernel_launch(void* const* d_in, const int* in_sizes, int n_in,
                              void* d_out, int out_size)
{
    const float* hs    = (const float*)d_in[0];
    const float* ln1g  = (const float*)d_in[1];
    const float* ln1b  = (const float*)d_in[2];
    const float* wattn = (const float*)d_in[3];
    const float* battn = (const float*)d_in[4];
    const float* wproj = (const float*)d_in[5];
    const float* bproj = (const float*)d_in[6];
    const float* ln2g  = (const float*)d_in[7];
    const float* ln2b  = (const float*)d_in[8];
    const float* wfc   = (const float*)d_in[9];
    const float* bfc   = (const float*)d_in[10];
    const float* wmlp  = (const float*)d_in[11];
    const float* bmlp  = (const float*)d_in[12];
    float* out = (float*)d_out;

    int tokens = in_sizes[0] / D;   // 8192
    int B = tokens / SEQ;

    float *xln, *qkvb, *attnb, *resb, *mlnb, *fcb;
    float *wattn_t, *wproj_t, *wfc_t, *wmlp_t;
    cudaGetSymbolAddress((void**)&xln,   g_xln);
    cudaGetSymbolAddress((void**)&qkvb,  g_qkv);
    cudaGetSymbolAddress((void**)&attnb, g_attn);
    cudaGetSymbolAddress((void**)&resb,  g_res);
    cudaGetSymbolAddress((void**)&mlnb,  g_mln);
    cudaGetSymbolAddress((void**)&fcb,   g_fc);
    cudaGetSymbolAddress((void**)&wattn_t, g_wattn_t);
    cudaGetSymbolAddress((void**)&wproj_t, g_wproj_t);
    cudaGetSymbolAddress((void**)&wfc_t,   g_wfc_t);
    cudaGetSymbolAddress((void**)&wmlp_t,  g_wmlp_t);

    cudaFuncSetAttribute(tc_gemm<0>, cudaFuncAttributeMaxDynamicSharedMemorySize, GSMEM);
    cudaFuncSetAttribute(tc_gemm<1>, cudaFuncAttributeMaxDynamicSharedMemorySize, GSMEM);
    cudaFuncSetAttribute(tc_gemm<2>, cudaFuncAttributeMaxDynamicSharedMemorySize, GSMEM);
    cudaFuncSetAttribute(attn_kernel, cudaFuncAttributeMaxDynamicSharedMemorySize, 98304);

    // weight transposes (Bt[N][K] K-major, tf32-rounded)
    transpose_kernel<<<dim3(3 * D / 32, D / 32), 256>>>(wattn, wattn_t, D, 3 * D);
    transpose_kernel<<<dim3(D / 32, D / 32), 256>>>(wproj, wproj_t, D, D);
    transpose_kernel<<<dim3(FF / 32, D / 32), 256>>>(wfc, wfc_t, D, FF);
    transpose_kernel<<<dim3(D / 32, FF / 32), 256>>>(wmlp, wmlp_t, FF, D);

    // LN1
    ln_kernel<<<tokens, 256>>>(hs, ln1g, ln1b, xln);

    // QKV = xln @ w_attn + b_attn
    tc_gemm<0><<<dim3(3 * D / BN, tokens / BM), 128, GSMEM>>>(
        xln, wattn_t, battn, nullptr, qkvb, tokens, 3 * D, D);

    // attention
    attn_kernel<<<dim3(SEQ / 128, H, B), 128, 98304>>>(qkvb, attnb);

    // resid = hs + attnb @ w_attn_proj + b_attn_proj
    tc_gemm<2><<<dim3(D / BN, tokens / BM), 128, GSMEM>>>(
        attnb, wproj_t, bproj, hs, resb, tokens, D, D);

    // LN2
    ln_kernel<<<tokens, 256>>>(resb, ln2g, ln2b, mlnb);

    // fc = gelu_new(mlnb @ w_fc + b_fc)   (rounded tf32)
    tc_gemm<1><<<dim3(FF / BN, tokens / BM), 128, GSMEM>>>(
        mlnb, wfc_t, bfc, nullptr, fcb, tokens, FF, D);

    // out = resb + fcb @ w_mlp_proj + b_mlp_proj
    tc_gemm<2><<<dim3(D / BN, tokens / BM), 128, GSMEM>>>(
        fcb, wmlp_t, bmlp, resb, out, tokens, D, FF);
}

// round 5
// speedup vs baseline: 3.4090x; 2.1245x over previous
#include <cuda_runtime.h>
#include <cstdint>

// Problem constants
#define D   1024
#define H   16
#define DH  64
#define FF  4096
#define SEQ 2048
#define MAXTOK 8192   // B=4 * S=2048

// ---------------- scratch (static device globals; no allocation) ----------------
__device__ float g_xln [MAXTOK * D];
__device__ float g_qkv [MAXTOK * 3 * D];
__device__ float g_attn[MAXTOK * D];
__device__ float g_res [MAXTOK * D];
__device__ float g_mln [MAXTOK * D];
__device__ float g_fc  [(size_t)MAXTOK * FF];
__device__ float g_wattn_t[3 * D * D];
__device__ float g_wproj_t[D * D];
__device__ float g_wfc_t  [FF * D];
__device__ float g_wmlp_t [D * FF];

// ---------------- helpers ----------------
__device__ __forceinline__ uint32_t smem_u32(const void* p){
    uint32_t a;
    asm("{ .reg .u64 t; cvta.to.shared.u64 t, %1; cvt.u32.u64 %0, t; }" : "=r"(a) : "l"(p));
    return a;
}
__device__ __forceinline__ float tf32r(float x){
    uint32_t u; asm("cvt.rna.tf32.f32 %0, %1;" : "=r"(u) : "f"(x));
    return __uint_as_float(u);
}
__device__ __forceinline__ void mma_tf32(float* c, const uint32_t* a, const uint32_t* b){
    asm volatile(
        "mma.sync.aligned.m16n8k8.row.col.f32.tf32.tf32.f32 "
        "{%0,%1,%2,%3}, {%4,%5,%6,%7}, {%8,%9}, {%0,%1,%2,%3};\n"
        : "+f"(c[0]), "+f"(c[1]), "+f"(c[2]), "+f"(c[3])
        : "r"(a[0]), "r"(a[1]), "r"(a[2]), "r"(a[3]), "r"(b[0]), "r"(b[1]));
}
__device__ __forceinline__ void cp16(uint32_t smem_addr, const void* gptr){
    asm volatile("cp.async.cg.shared.global [%0], [%1], 16;" :: "r"(smem_addr), "l"(gptr));
}

// ---------------- transpose: in[R][C] -> out[C][R], rounded to tf32 ----------------
__global__ __launch_bounds__(256) void transpose_kernel(const float* __restrict__ in,
                                                        float* __restrict__ out, int R, int C)
{
    __shared__ float t[32][33];
    int bx = blockIdx.x * 32, by = blockIdx.y * 32;
    int x = threadIdx.x & 31, y0 = threadIdx.x >> 5;
    #pragma unroll
    for (int yy = y0; yy < 32; yy += 8)
        t[yy][x] = in[(size_t)(by + yy) * C + bx + x];
    __syncthreads();
    #pragma unroll
    for (int yy = y0; yy < 32; yy += 8)
        out[(size_t)(bx + yy) * R + by + x] = tf32r(t[x][yy]);
}

// ---------------- LayerNorm (output rounded to tf32: feeds GEMM A) ----------------
__global__ __launch_bounds__(256) void ln_kernel(const float* __restrict__ in,
                                                 const float* __restrict__ gw,
                                                 const float* __restrict__ bw,
                                                 float* __restrict__ out)
{
    __shared__ float red0[8], red1[8];
    int row = blockIdx.x, tid = threadIdx.x;
    const float4* x4 = (const float4*)(in + (size_t)row * D);
    float4 v = x4[tid];
    float s  = v.x + v.y + v.z + v.w;
    float ss = v.x*v.x + v.y*v.y + v.z*v.z + v.w*v.w;
    #pragma unroll
    for (int o = 16; o; o >>= 1) {
        s  += __shfl_xor_sync(0xffffffffu, s,  o);
        ss += __shfl_xor_sync(0xffffffffu, ss, o);
    }
    if ((tid & 31) == 0) { red0[tid >> 5] = s; red1[tid >> 5] = ss; }
    __syncthreads();
    s = 0.f; ss = 0.f;
    #pragma unroll
    for (int i = 0; i < 8; i++) { s += red0[i]; ss += red1[i]; }
    float mean = s * (1.f / D);
    float var  = ss * (1.f / D) - mean * mean;
    float rstd = rsqrtf(var + 1e-5f);
    float4 gv = ((const float4*)gw)[tid];
    float4 bv = ((const float4*)bw)[tid];
    float4 o4;
    o4.x = tf32r((v.x - mean) * rstd * gv.x + bv.x);
    o4.y = tf32r((v.y - mean) * rstd * gv.y + bv.y);
    o4.z = tf32r((v.z - mean) * rstd * gv.z + bv.z);
    o4.w = tf32r((v.w - mean) * rstd * gv.w + bv.w);
    ((float4*)(out + (size_t)row * D))[tid] = o4;
}

// ============== mma.sync tf32 GEMM: C[M,N] = A[M,K] @ Bt[N,K]^T + epilogue ==============
#define BM 128
#define BN 128
#define BK 32
#define LDT 36
#define TBUF (128 * LDT)
#define GSMEM (4 * TBUF * 4)

template<int EPI>
__global__ __launch_bounds__(128) void tc_gemm(const float* __restrict__ A,
                                               const float* __restrict__ Bt,
                                               const float* __restrict__ bias,
                                               const float* __restrict__ res,
                                               float* __restrict__ C,
                                               int M, int N_, int K)
{
    extern __shared__ float smem[];
    float* AsBase = smem;
    float* BsBase = smem + 2 * TBUF;
    const int tid = threadIdx.x, lane = tid & 31, wid = tid >> 5;
    const int wm = (wid >> 1) * 64, wn = (wid & 1) * 64;
    const int bm = blockIdx.y * BM, bn = blockIdx.x * BN;
    const int nch = K / BK;

    const float* Ag = A  + (size_t)bm * K;
    const float* Bg = Bt + (size_t)bn * K;

    float acc[4][8][4];
    #pragma unroll
    for (int mf = 0; mf < 4; mf++)
        #pragma unroll
        for (int nf = 0; nf < 8; nf++)
            #pragma unroll
            for (int q = 0; q < 4; q++) acc[mf][nf][q] = 0.f;

    auto load_chunk = [&](int c, int buf) {
        float* dA = AsBase + buf * TBUF;
        float* dB = BsBase + buf * TBUF;
        const float* a0 = Ag + c * BK;
        const float* b0 = Bg + c * BK;
        #pragma unroll
        for (int i = 0; i < 8; i++) {
            int slot = i * 128 + tid;
            int r = slot >> 3, u = slot & 7;
            cp16(smem_u32(dA + r * LDT + u * 4), a0 + (size_t)r * K + u * 4);
            cp16(smem_u32(dB + r * LDT + u * 4), b0 + (size_t)r * K + u * 4);
        }
        asm volatile("cp.async.commit_group;" ::: "memory");
    };

    load_chunk(0, 0);

    for (int c = 0; c < nch; c++) {
        if (c + 1 < nch) {
            load_chunk(c + 1, (c + 1) & 1);
            asm volatile("cp.async.wait_group 1;" ::: "memory");
        } else {
            asm volatile("cp.async.wait_group 0;" ::: "memory");
        }
        __syncthreads();
        const float* cA = AsBase + (c & 1) * TBUF;
        const float* cB = BsBase + (c & 1) * TBUF;
        #pragma unroll
        for (int ks = 0; ks < 4; ks++) {
            const int k0 = ks * 8 + (lane & 3);
            uint32_t a[4][4], b[8][2];
            #pragma unroll
            for (int mf = 0; mf < 4; mf++) {
                const float* p = cA + (wm + mf * 16 + (lane >> 2)) * LDT + k0;
                a[mf][0] = __float_as_uint(p[0]);
                a[mf][1] = __float_as_uint(p[8 * LDT]);
                a[mf][2] = __float_as_uint(p[4]);
                a[mf][3] = __float_as_uint(p[8 * LDT + 4]);
            }
            #pragma unroll
            for (int nf = 0; nf < 8; nf++) {
                const float* p = cB + (wn + nf * 8 + (lane >> 2)) * LDT + k0;
                b[nf][0] = __float_as_uint(p[0]);
                b[nf][1] = __float_as_uint(p[4]);
            }
            #pragma unroll
            for (int mf = 0; mf < 4; mf++)
                #pragma unroll
                for (int nf = 0; nf < 8; nf++)
                    mma_tf32(acc[mf][nf], a[mf], b[nf]);
        }
        __syncthreads();
    }

    const float GC = 0.7978845608028654f;
    #pragma unroll
    for (int mf = 0; mf < 4; mf++) {
        #pragma unroll
        for (int half = 0; half < 2; half++) {
            int row = bm + wm + mf * 16 + (lane >> 2) + half * 8;
            float* Crow = C + (size_t)row * N_ + bn + wn;
            const float* Rrow = res + (size_t)row * N_ + bn + wn;
            #pragma unroll
            for (int nf = 0; nf < 8; nf++) {
                int col = nf * 8 + 2 * (lane & 3);
                float2 v;
                v.x = acc[mf][nf][half * 2 + 0] + bias[bn + wn + col];
                v.y = acc[mf][nf][half * 2 + 1] + bias[bn + wn + col + 1];
                if (EPI == 1) {
                    v.x = tf32r(0.5f * v.x * (1.f + tanhf(GC * (v.x + 0.044715f * v.x * v.x * v.x))));
                    v.y = tf32r(0.5f * v.y * (1.f + tanhf(GC * (v.y + 0.044715f * v.y * v.y * v.y))));
                }
                if (EPI == 2) {
                    float2 rv = *(const float2*)(Rrow + col);
                    v.x += rv.x; v.y += rv.y;
                }
                *(float2*)(Crow + col) = v;
            }
        }
    }
}

// ============== Flash attention (causal) with tf32 mma.sync ==============
// Q-tile 128 (4 warps x 32 rows), K-tile 64, DH=64. cp.async double-buffered K/V.
// smem stride 68 floats (conflict-free fragment loads).
#define AST 68
#define ASMEM ((2 * 128 + 4 * 64) * AST * 4)   // 139264 B

__global__ __launch_bounds__(128) void attn_kernel(const float* __restrict__ qkv,
                                                   float* __restrict__ out)
{
    extern __shared__ float smem[];
    float* Qs  = smem;                        // 128 x AST
    float* Ps  = Qs  + 128 * AST;             // 128 x AST
    float* KsB = Ps  + 128 * AST;             // 2 x 64 x AST
    float* VsB = KsB + 2 * 64 * AST;          // 2 x 64 x AST

    const int b = blockIdx.z, h = blockIdx.y, q0 = blockIdx.x << 7;
    const int tid = threadIdx.x, lane = tid & 31, wid = tid >> 5;
    const int wm = wid * 32;                  // warp's q-row offset in tile
    const int lp = lane >> 2, lq = lane & 3;  // fragment lane coords
    const size_t base = (size_t)b * SEQ * (3 * D) + h * DH;

    // load Q tile, scaled by 1/sqrt(DH)=0.125, tf32-rounded
    for (int s = tid; s < 2048; s += 128) {
        int r = s >> 4, u = s & 15;
        float4 v = *(const float4*)(qkv + base + (size_t)(q0 + r) * (3 * D) + u * 4);
        float* dst = Qs + r * AST + u * 4;
        dst[0] = tf32r(v.x * 0.125f); dst[1] = tf32r(v.y * 0.125f);
        dst[2] = tf32r(v.z * 0.125f); dst[3] = tf32r(v.w * 0.125f);
    }

    auto load_kv = [&](int kt, int buf) {
        float* dK = KsB + buf * 64 * AST;
        float* dV = VsB + buf * 64 * AST;
        const int k0 = kt << 6;
        #pragma unroll
        for (int i = 0; i < 8; i++) {
            int s = i * 128 + tid;
            int r = s >> 4, u = s & 15;
            const float* p = qkv + base + (size_t)(k0 + r) * (3 * D) + u * 4;
            cp16(smem_u32(dK + r * AST + u * 4), p + D);
            cp16(smem_u32(dV + r * AST + u * 4), p + 2 * D);
        }
        asm volatile("cp.async.commit_group;" ::: "memory");
    };

    float m_i[2][2], l_i[2][2], ao[2][8][4];
    #pragma unroll
    for (int mf = 0; mf < 2; mf++)
        #pragma unroll
        for (int hf = 0; hf < 2; hf++) { m_i[mf][hf] = -1e30f; l_i[mf][hf] = 0.f; }
    #pragma unroll
    for (int mf = 0; mf < 2; mf++)
        #pragma unroll
        for (int nf = 0; nf < 8; nf++)
            #pragma unroll
            for (int q = 0; q < 4; q++) ao[mf][nf][q] = 0.f;

    const int ntiles = (q0 >> 6) + 2;
    load_kv(0, 0);
    __syncthreads();       // Q visible to all before compute (also covers first tile ordering)

    for (int kt = 0; kt < ntiles; kt++) {
        const int buf = kt & 1;
        const int k0 = kt << 6;
        if (kt + 1 < ntiles) {
            load_kv(kt + 1, buf ^ 1);
            asm volatile("cp.async.wait_group 1;" ::: "memory");
        } else {
            asm volatile("cp.async.wait_group 0;" ::: "memory");
        }
        __syncthreads();   // tile kt data visible to all
        const float* Ks = KsB + buf * 64 * AST;
        const float* Vs = VsB + buf * 64 * AST;

        // ---- S = Q K^T : warptile 32(M) x 64(N), 8 k-chunks over d ----
        float sc[2][8][4];
        #pragma unroll
        for (int mf = 0; mf < 2; mf++)
            #pragma unroll
            for (int nf = 0; nf < 8; nf++)
                #pragma unroll
                for (int q = 0; q < 4; q++) sc[mf][nf][q] = 0.f;
        #pragma unroll
        for (int kc = 0; kc < 8; kc++) {
            const int kk = kc * 8 + lq;
            uint32_t a[2][4], bfr[8][2];
            #pragma unroll
            for (int mf = 0; mf < 2; mf++) {
                const float* p = Qs + (wm + mf * 16 + lp) * AST + kk;
                a[mf][0] = __float_as_uint(p[0]);
                a[mf][1] = __float_as_uint(p[8 * AST]);
                a[mf][2] = __float_as_uint(p[4]);
                a[mf][3] = __float_as_uint(p[8 * AST + 4]);
            }
            #pragma unroll
            for (int nf = 0; nf < 8; nf++) {
                const float* p = Ks + (nf * 8 + lp) * AST + kk;
                bfr[nf][0] = __float_as_uint(p[0]);
                bfr[nf][1] = __float_as_uint(p[4]);
            }
            #pragma unroll
            for (int mf = 0; mf < 2; mf++)
                #pragma unroll
                for (int nf = 0; nf < 8; nf++)
                    mma_tf32(sc[mf][nf], a[mf], bfr[nf]);
        }

        // ---- causal mask on last two tiles ----
        if (kt >= ntiles - 2) {
            #pragma unroll
            for (int mf = 0; mf < 2; mf++)
                #pragma unroll
                for (int hf = 0; hf < 2; hf++) {
                    int row = q0 + wm + mf * 16 + lp + hf * 8;
                    #pragma unroll
                    for (int nf = 0; nf < 8; nf++) {
                        int col = k0 + nf * 8 + 2 * lq;
                        if (col > row)     sc[mf][nf][hf * 2 + 0] = -10000.0f;
                        if (col + 1 > row) sc[mf][nf][hf * 2 + 1] = -10000.0f;
                    }
                }
        }

        // ---- online softmax per row-slot (mf, hf) ----
        #pragma unroll
        for (int mf = 0; mf < 2; mf++)
            #pragma unroll
            for (int hf = 0; hf < 2; hf++) {
                float mx = sc[mf][0][hf * 2];
                #pragma unroll
                for (int nf = 0; nf < 8; nf++) {
                    mx = fmaxf(mx, sc[mf][nf][hf * 2 + 0]);
                    mx = fmaxf(mx, sc[mf][nf][hf * 2 + 1]);
                }
                mx = fmaxf(mx, __shfl_xor_sync(0xffffffffu, mx, 1, 4));
                mx = fmaxf(mx, __shfl_xor_sync(0xffffffffu, mx, 2, 4));
                float mnew = fmaxf(m_i[mf][hf], mx);
                float corr = __expf(m_i[mf][hf] - mnew);
                float sum = 0.f;
                #pragma unroll
                for (int nf = 0; nf < 8; nf++) {
                    float p0 = __expf(sc[mf][nf][hf * 2 + 0] - mnew);
                    float p1 = __expf(sc[mf][nf][hf * 2 + 1] - mnew);
                    sc[mf][nf][hf * 2 + 0] = p0;
                    sc[mf][nf][hf * 2 + 1] = p1;
                    sum += p0 + p1;
                }
                sum += __shfl_xor_sync(0xffffffffu, sum, 1, 4);
                sum += __shfl_xor_sync(0xffffffffu, sum, 2, 4);
                l_i[mf][hf] = l_i[mf][hf] * corr + sum;
                m_i[mf][hf] = mnew;
                #pragma unroll
                for (int nf = 0; nf < 8; nf++) {
                    ao[mf][nf][hf * 2 + 0] *= corr;
                    ao[mf][nf][hf * 2 + 1] *= corr;
                }
            }

        // ---- stage P into warp-private smem rows (C-layout -> A-layout reload) ----
        #pragma unroll
        for (int mf = 0; mf < 2; mf++) {
            int row0 = wm + mf * 16 + lp;
            #pragma unroll
            for (int nf = 0; nf < 8; nf++) {
                int col = nf * 8 + 2 * lq;
                *(float2*)(Ps + row0 * AST + col)       = make_float2(sc[mf][nf][0], sc[mf][nf][1]);
                *(float2*)(Ps + (row0 + 8) * AST + col) = make_float2(sc[mf][nf][2], sc[mf][nf][3]);
            }
        }
        __syncwarp();

        // ---- O += P V : 8 k-chunks over keys; B frags read row-major V with swapped roles ----
        #pragma unroll
        for (int kc = 0; kc < 8; kc++) {
            const int kk = kc * 8 + lq;
            uint32_t a[2][4], bfr[8][2];
            #pragma unroll
            for (int mf = 0; mf < 2; mf++) {
                const float* p = Ps + (wm + mf * 16 + lp) * AST + kk;
                a[mf][0] = __float_as_uint(p[0]);
                a[mf][1] = __float_as_uint(p[8 * AST]);
                a[mf][2] = __float_as_uint(p[4]);
                a[mf][3] = __float_as_uint(p[8 * AST + 4]);
            }
            #pragma unroll
            for (int nf = 0; nf < 8; nf++) {
                const float* p0 = Vs + kk * AST + nf * 8 + lp;        // key = kk,   d = nf*8+lp
                const float* p1 = Vs + (kk + 4) * AST + nf * 8 + lp;  // key = kk+4
                bfr[nf][0] = __float_as_uint(p0[0]);
                bfr[nf][1] = __float_as_uint(p1[0]);
            }
            #pragma unroll
            for (int mf = 0; mf < 2; mf++)
                #pragma unroll
                for (int nf = 0; nf < 8; nf++)
                    mma_tf32(ao[mf][nf], a[mf], bfr[nf]);
        }
        __syncthreads();   // all warps done with this K/V buffer before next prefetch overwrites
    }

    // ---- write O (tf32-rounded: feeds attn-proj GEMM as A) ----
    #pragma unroll
    for (int mf = 0; mf < 2; mf++)
        #pragma unroll
        for (int hf = 0; hf < 2; hf++) {
            float inv = 1.f / l_i[mf][hf];
            int row = q0 + wm + mf * 16 + lp + hf * 8;
            float* orow = out + (size_t)(b * SEQ + row) * D + h * DH;
            #pragma unroll
            for (int nf = 0; nf < 8; nf++) {
                int col = nf * 8 + 2 * lq;
                *(float2*)(orow + col) = make_float2(tf32r(ao[mf][nf][hf * 2 + 0] * inv),
                                                     tf32r(ao[mf][nf][hf * 2 + 1] * inv));
            }
        }
}

// ---------------- launch ----------------
extern "C" void kernel_launch(void* const* d_in, const int* in_sizes, int n_in,
                              void* d_out, int out_size)
{
    const float* hs    = (const float*)d_in[0];
    const float* ln1g  = (const float*)d_in[1];
    const float* ln1b  = (const float*)d_in[2];
    const float* wattn = (const float*)d_in[3];
    const float* battn = (const float*)d_in[4];
    const float* wproj = (const float*)d_in[5];
    const float* bproj = (const float*)d_in[6];
    const float* ln2g  = (const float*)d_in[7];
    const float* ln2b  = (const float*)d_in[8];
    const float* wfc   = (const float*)d_in[9];
    const float* bfc   = (const float*)d_in[10];
    const float* wmlp  = (const float*)d_in[11];
    const float* bmlp  = (const float*)d_in[12];
    float* out = (float*)d_out;

    int tokens = in_sizes[0] / D;   // 8192
    int B = tokens / SEQ;

    float *xln, *qkvb, *attnb, *resb, *mlnb, *fcb;
    float *wattn_t, *wproj_t, *wfc_t, *wmlp_t;
    cudaGetSymbolAddress((void**)&xln,   g_xln);
    cudaGetSymbolAddress((void**)&qkvb,  g_qkv);
    cudaGetSymbolAddress((void**)&attnb, g_attn);
    cudaGetSymbolAddress((void**)&resb,  g_res);
    cudaGetSymbolAddress((void**)&mlnb,  g_mln);
    cudaGetSymbolAddress((void**)&fcb,   g_fc);
    cudaGetSymbolAddress((void**)&wattn_t, g_wattn_t);
    cudaGetSymbolAddress((void**)&wproj_t, g_wproj_t);
    cudaGetSymbolAddress((void**)&wfc_t,   g_wfc_t);
    cudaGetSymbolAddress((void**)&wmlp_t,  g_wmlp_t);

    cudaFuncSetAttribute(tc_gemm<0>, cudaFuncAttributeMaxDynamicSharedMemorySize, GSMEM);
    cudaFuncSetAttribute(tc_gemm<1>, cudaFuncAttributeMaxDynamicSharedMemorySize, GSMEM);
    cudaFuncSetAttribute(tc_gemm<2>, cudaFuncAttributeMaxDynamicSharedMemorySize, GSMEM);
    cudaFuncSetAttribute(attn_kernel, cudaFuncAttributeMaxDynamicSharedMemorySize, ASMEM);

    // weight transposes (Bt[N][K] K-major, tf32-rounded)
    transpose_kernel<<<dim3(3 * D / 32, D / 32), 256>>>(wattn, wattn_t, D, 3 * D);
    transpose_kernel<<<dim3(D / 32, D / 32), 256>>>(wproj, wproj_t, D, D);
    transpose_kernel<<<dim3(FF / 32, D / 32), 256>>>(wfc, wfc_t, D, FF);
    transpose_kernel<<<dim3(D / 32, FF / 32), 256>>>(wmlp, wmlp_t, FF, D);

    // LN1
    ln_kernel<<<tokens, 256>>>(hs, ln1g, ln1b, xln);

    // QKV = xln @ w_attn + b_attn
    tc_gemm<0><<<dim3(3 * D / BN, tokens / BM), 128, GSMEM>>>(
        xln, wattn_t, battn, nullptr, qkvb, tokens, 3 * D, D);

    // attention (tf32 mma flash attention)
    attn_kernel<<<dim3(SEQ / 128, H, B), 128, ASMEM>>>(qkvb, attnb);

    // resid = hs + attnb @ w_attn_proj + b_attn_proj
    tc_gemm<2><<<dim3(D / BN, tokens / BM), 128, GSMEM>>>(
        attnb, wproj_t, bproj, hs, resb, tokens, D, D);

    // LN2
    ln_kernel<<<tokens, 256>>>(resb, ln2g, ln2b, mlnb);

    // fc = gelu_new(mlnb @ w_fc + b_fc)
    tc_gemm<1><<<dim3(FF / BN, tokens / BM), 128, GSMEM>>>(
        mlnb, wfc_t, bfc, nullptr, fcb, tokens, FF, D);

    // out = resb + fcb @ w_mlp_proj + b_mlp_proj
    tc_gemm<2><<<dim3(D / BN, tokens / BM), 128, GSMEM>>>(
        fcb, wmlp_t, bmlp, resb, out, tokens, D, FF);
}